// round 2
// baseline (speedup 1.0000x reference)
#include <cuda_runtime.h>

// Hybrid quantum model: 2560 independent 10-qubit statevector sims + linear head.
// State lives in shared memory (swizzled), gates fused & applied in 16-amp register cubes.

#define NC   320
#define NLAY 5

__device__ float g_z[2560];   // z0 expectation values, [b*320 + c]

__device__ __forceinline__ float2 cmul(float2 a, float2 b) {
    return make_float2(a.x*b.x - a.y*b.y, a.x*b.y + a.y*b.x);
}
__device__ __forceinline__ float2 cadd(float2 a, float2 b) {
    return make_float2(a.x + b.x, a.y + b.y);
}
__device__ __forceinline__ unsigned sw(unsigned i) { return i ^ ((i >> 5) & 31u); }

// Fused controlled gate: U = RY(pi/4) @ RZ(pi/2) @ X  (constant)
template<int CB, int TB>
__device__ __forceinline__ void cu_gate(float2* v) {
    const float2 u00 = make_float2(-0.2705980500730985f, -0.2705980500730985f);
    const float2 u01 = make_float2( 0.6532814824381883f, -0.6532814824381883f);
    const float2 u10 = make_float2( 0.6532814824381883f,  0.6532814824381883f);
    const float2 u11 = make_float2( 0.2705980500730985f, -0.2705980500730985f);
#pragma unroll
    for (int k = 0; k < 16; ++k) {
        if ((k & CB) && !(k & TB)) {
            float2 a = v[k], b = v[k | TB];
            v[k]      = cadd(cmul(u00, a), cmul(u01, b));
            v[k | TB] = cadd(cmul(u10, a), cmul(u11, b));
        }
    }
}

// General single-qubit gate from precomputed matrix (4 complex in smem)
template<int TB>
__device__ __forceinline__ void sq_gate(float2* v, const float2* m) {
    float2 m00 = m[0], m01 = m[1], m10 = m[2], m11 = m[3];
#pragma unroll
    for (int k = 0; k < 16; ++k) {
        if (!(k & TB)) {
            float2 a = v[k], b = v[k | TB];
            v[k]      = cadd(cmul(m00, a), cmul(m01, b));
            v[k | TB] = cadd(cmul(m10, a), cmul(m11, b));
        }
    }
}

__global__ void __launch_bounds__(256, 2)
qsim_kernel(const float* __restrict__ x,  const float* __restrict__ W1,
            const float* __restrict__ b1, const float* __restrict__ qw)
{
    __shared__ float2 psi[4][1024];   // 4 states (same circuit, 4 batch rows)
    __shared__ float2 rm[50][4];      // rot matrices: [layer*10+qubit][m00,m01,m10,m11]
    __shared__ float  red[8];

    const int tid = threadIdx.x;
    const int g   = tid >> 6;          // state group 0..3
    const int t   = tid & 63;
    const int c   = blockIdx.x >> 1;   // circuit index
    const int bh  = blockIdx.x & 1;    // batch half
    const int b   = bh * 4 + g;        // batch row 0..7

    // embedding angle h[b][c] = x[b] . W1[c] + b1[c]
    float hang = x[b*2+0]*W1[c*2+0] + x[b*2+1]*W1[c*2+1] + b1[c];
    float se, ce;
    sincosf(0.5f * hang, &se, &ce);

    // Precompute rot matrices  M = RZ(w2) RY(w1) RZ(w0)  (shared across batch)
    if (tid < 50) {
        int l = tid / 10, q = tid - l * 10;
        const float* wp = qw + ((c*NLAY + l)*10 + q) * 3;
        float w0 = wp[0], w1v = wp[1], w2 = wp[2];
        float sy, cy; sincosf(0.5f * w1v,       &sy, &cy);
        float sp, cp; sincosf(0.5f * (w0 + w2), &sp, &cp);
        float sm, cm; sincosf(0.5f * (w0 - w2), &sm, &cm);
        rm[tid][0] = make_float2( cy*cp, -cy*sp);
        rm[tid][1] = make_float2(-sy*cm, -sy*sm);
        rm[tid][2] = make_float2( sy*cm, -sy*sm);
        rm[tid][3] = make_float2( cy*cp,  cy*sp);
    }

    // |0..0> then H on all qubits = uniform state, amp = 2^-5
#pragma unroll
    for (int k = 0; k < 16; ++k) psi[g][t + k*64] = make_float2(0.03125f, 0.0f);
    __syncthreads();

    float2 v[16];

    for (int l = 0; l < NLAY; ++l) {
        // ---------- Pass A: qubits 0-3 (cube masks 8,4,2,1) ----------
#pragma unroll
        for (int k = 0; k < 16; ++k) { unsigned i = t + (k << 6); v[k] = psi[g][sw(i)]; }
        // embedding on qubit 0 (mask 8): RY for even layers, RZ for odd
        if ((l & 1) == 0) {
#pragma unroll
            for (int k = 0; k < 8; ++k) {
                float2 a = v[k], bb = v[k + 8];
                v[k]     = make_float2(ce*a.x - se*bb.x, ce*a.y - se*bb.y);
                v[k + 8] = make_float2(se*a.x + ce*bb.x, se*a.y + ce*bb.y);
            }
        } else {
            float2 f0 = make_float2(ce, -se), f1 = make_float2(ce, se);
#pragma unroll
            for (int k = 0; k < 16; ++k) v[k] = cmul((k & 8) ? f1 : f0, v[k]);
        }
        cu_gate<8, 4>(v); cu_gate<4, 2>(v); cu_gate<2, 1>(v);
        if (l < 4) {   // last layer's rots on q!=0 commute with Z0 -> dropped
            sq_gate<8>(v, rm[l*10 + 0]);
            sq_gate<4>(v, rm[l*10 + 1]);
            sq_gate<2>(v, rm[l*10 + 2]);
        }
#pragma unroll
        for (int k = 0; k < 16; ++k) { unsigned i = t + (k << 6); psi[g][sw(i)] = v[k]; }
        __syncthreads();

        // ---------- Pass B: qubits 3-6 ----------
        {
            unsigned base = ((unsigned)(t >> 3) << 7) | (unsigned)(t & 7);
#pragma unroll
            for (int k = 0; k < 16; ++k) { unsigned i = base + (k << 3); v[k] = psi[g][sw(i)]; }
            cu_gate<8, 4>(v); cu_gate<4, 2>(v); cu_gate<2, 1>(v);
            if (l < 4) {
                sq_gate<8>(v, rm[l*10 + 3]);
                sq_gate<4>(v, rm[l*10 + 4]);
                sq_gate<2>(v, rm[l*10 + 5]);
            }
#pragma unroll
            for (int k = 0; k < 16; ++k) { unsigned i = base + (k << 3); psi[g][sw(i)] = v[k]; }
        }
        __syncthreads();

        // ---------- Pass C: qubits 6-9 ----------
        {
#pragma unroll
            for (int k = 0; k < 16; ++k) { unsigned i = ((unsigned)t << 4) | k; v[k] = psi[g][sw(i)]; }
            cu_gate<8, 4>(v); cu_gate<4, 2>(v); cu_gate<2, 1>(v);
            if (l < 4) {
                sq_gate<8>(v, rm[l*10 + 6]);
                sq_gate<4>(v, rm[l*10 + 7]);
                sq_gate<2>(v, rm[l*10 + 8]);
                sq_gate<1>(v, rm[l*10 + 9]);
            }
#pragma unroll
            for (int k = 0; k < 16; ++k) { unsigned i = ((unsigned)t << 4) | k; psi[g][sw(i)] = v[k]; }
        }
        __syncthreads();
    }

    // ---------- Measurement: <Z0> with trailing qubit-0 gate G = H * R * R ----------
#pragma unroll
    for (int k = 0; k < 16; ++k) { unsigned i = t + (k << 6); v[k] = psi[g][sw(i)]; }
    float2 r00 = rm[40][0], r01 = rm[40][1], r10 = rm[40][2], r11 = rm[40][3];
    float2 s00 = cadd(cmul(r00, r00), cmul(r01, r10));
    float2 s01 = cadd(cmul(r00, r01), cmul(r01, r11));
    float2 s10 = cadd(cmul(r10, r00), cmul(r11, r10));
    float2 s11 = cadd(cmul(r10, r01), cmul(r11, r11));
    const float is2 = 0.7071067811865476f;
    float2 g00 = make_float2(is2*(s00.x + s10.x), is2*(s00.y + s10.y));
    float2 g01 = make_float2(is2*(s01.x + s11.x), is2*(s01.y + s11.y));
    float2 g10 = make_float2(is2*(s00.x - s10.x), is2*(s00.y - s10.y));
    float2 g11 = make_float2(is2*(s01.x - s11.x), is2*(s01.y - s11.y));

    float acc = 0.f;
#pragma unroll
    for (int k = 0; k < 8; ++k) {
        float2 a = v[k], bb = v[k + 8];
        float2 na = cadd(cmul(g00, a), cmul(g01, bb));
        float2 nb = cadd(cmul(g10, a), cmul(g11, bb));
        acc += na.x*na.x + na.y*na.y - nb.x*nb.x - nb.y*nb.y;
    }
#pragma unroll
    for (int off = 16; off > 0; off >>= 1) acc += __shfl_down_sync(0xffffffffu, acc, off);
    if ((tid & 31) == 0) red[tid >> 5] = acc;
    __syncthreads();
    if (tid < 4) g_z[(bh*4 + tid)*NC + c] = red[2*tid] + red[2*tid + 1];
}

// Head: logits = z @ W2^T + b2, softmax per row. One warp per batch row.
__global__ void __launch_bounds__(256)
head_kernel(const float* __restrict__ W2, const float* __restrict__ b2,
            float* __restrict__ out)
{
    int b    = threadIdx.x >> 5;
    int lane = threadIdx.x & 31;
    float p0 = 0.f, p1 = 0.f;
    for (int cc = lane; cc < NC; cc += 32) {
        float zv = g_z[b*NC + cc];
        p0 = fmaf(zv, W2[cc],      p0);
        p1 = fmaf(zv, W2[NC + cc], p1);
    }
#pragma unroll
    for (int off = 16; off > 0; off >>= 1) {
        p0 += __shfl_down_sync(0xffffffffu, p0, off);
        p1 += __shfl_down_sync(0xffffffffu, p1, off);
    }
    if (lane == 0) {
        float l0 = p0 + b2[0], l1 = p1 + b2[1];
        float m  = fmaxf(l0, l1);
        float e0 = expf(l0 - m), e1 = expf(l1 - m);
        float inv = 1.0f / (e0 + e1);
        out[2*b + 0] = e0 * inv;
        out[2*b + 1] = e1 * inv;
    }
}

extern "C" void kernel_launch(void* const* d_in, const int* in_sizes, int n_in,
                              void* d_out, int out_size) {
    const float* x  = (const float*)d_in[0];   // (8,2)
    const float* W1 = (const float*)d_in[1];   // (320,2)
    const float* b1 = (const float*)d_in[2];   // (320,)
    const float* qw = (const float*)d_in[3];   // (320,5,10,3)
    const float* W2 = (const float*)d_in[4];   // (2,320)
    const float* b2 = (const float*)d_in[5];   // (2,)
    float* out = (float*)d_out;                // (8,2)

    qsim_kernel<<<640, 256>>>(x, W1, b1, qw);
    head_kernel<<<1, 256>>>(W2, b2, out);
}

// round 3
// speedup vs baseline: 1.2207x; 1.2207x over previous
#include <cuda_runtime.h>

// Hybrid quantum model, v2: packed f32x2 math, warp-private states.
// One warp simulates one 10-qubit state (1024 amps) held entirely in registers
// as 16 packed pairs/thread (SoA re/im, pair = amp bit0). SMEM is only a
// transpose buffer between the 3 bit-group passes; __syncwarp only.

#define NC   320
#define NLAY 5

typedef unsigned long long u64;

__device__ float g_acc[16];   // partial logits [batch][2], self-reset by finalize

// ---------------- packed f32x2 helpers ----------------
__device__ __forceinline__ u64 pack2(float x, float y) {
    u64 u; asm("mov.b64 %0,{%1,%2};" : "=l"(u) : "f"(x), "f"(y)); return u;
}
__device__ __forceinline__ float2 unpk(u64 u) {
    float2 v; asm("mov.b64 {%0,%1},%2;" : "=f"(v.x), "=f"(v.y) : "l"(u)); return v;
}
__device__ __forceinline__ u64 bc(float x) { return pack2(x, x); }
__device__ __forceinline__ u64 ffma2(u64 a, u64 b, u64 c) {
    u64 d; asm("fma.rn.f32x2 %0,%1,%2,%3;" : "=l"(d) : "l"(a), "l"(b), "l"(c)); return d;
}
__device__ __forceinline__ u64 fmul2(u64 a, u64 b) {
    u64 d; asm("mul.rn.f32x2 %0,%1,%2;" : "=l"(d) : "l"(a), "l"(b)); return d;
}
__device__ __forceinline__ u64 fadd2(u64 a, u64 b) {
    u64 d; asm("add.rn.f32x2 %0,%1,%2;" : "=l"(d) : "l"(a), "l"(b)); return d;
}
__device__ __forceinline__ u64 neg2(u64 a) { return a ^ 0x8000000080000000ull; }

__device__ __forceinline__ float2 cmul(float2 a, float2 b) {
    return make_float2(a.x*b.x - a.y*b.y, a.x*b.y + a.y*b.x);
}
__device__ __forceinline__ float2 cadd(float2 a, float2 b) {
    return make_float2(a.x + b.x, a.y + b.y);
}

// general complex 2x2 butterfly on packed pairs (16 f32x2 ops)
struct M12 { u64 x00,y00,yn00,x01,y01,yn01,x10,y10,yn10,x11,y11,yn11; };

__device__ __forceinline__ M12 mkM(float2 m00, float2 m01, float2 m10, float2 m11) {
    M12 m;
    m.x00=bc(m00.x); m.y00=bc(m00.y); m.yn00=bc(-m00.y);
    m.x01=bc(m01.x); m.y01=bc(m01.y); m.yn01=bc(-m01.y);
    m.x10=bc(m10.x); m.y10=bc(m10.y); m.yn10=bc(-m10.y);
    m.x11=bc(m11.x); m.y11=bc(m11.y); m.yn11=bc(-m11.y);
    return m;
}
__device__ __forceinline__ void bfly(u64& ar, u64& ai, u64& br, u64& bi, const M12& m) {
    u64 nar = ffma2(m.x00,ar, ffma2(m.yn00,ai, ffma2(m.x01,br, fmul2(m.yn01,bi))));
    u64 nai = ffma2(m.y00,ar, ffma2(m.x00, ai, ffma2(m.y01,br, fmul2(m.x01, bi))));
    u64 nbr = ffma2(m.x10,ar, ffma2(m.yn10,ai, ffma2(m.x11,br, fmul2(m.yn11,bi))));
    u64 nbi = ffma2(m.y10,ar, ffma2(m.x10, ai, ffma2(m.y11,br, fmul2(m.x11, bi))));
    ar=nar; ai=nai; br=nbr; bi=nbi;
}

// CU gate = RY(pi/4)RZ(pi/2)X: u00=(A,A) u01=(B,-B) u10=(B,B) u11=(-A,A), A=-0.2706,B=0.6533
#define CU_A (-0.2705980500730985f)
#define CU_B ( 0.6532814824381883f)
__device__ __forceinline__ void cu_bfly(u64& ar, u64& ai, u64& br, u64& bi,
                                        u64 Ap, u64 An, u64 Bp, u64 Bn, u64 mOne) {
    u64 d1 = ffma2(mOne, ai, ar);   // ar - ai
    u64 s1 = fadd2(ar, ai);
    u64 s2 = fadd2(br, bi);
    u64 d2 = ffma2(mOne, bi, br);   // br - bi
    ar = ffma2(Ap, d1, fmul2(Bp, s2));   // A*d1 + B*s2
    ai = ffma2(Ap, s1, fmul2(Bn, d2));   // A*s1 - B*d2
    br = ffma2(Bp, d1, fmul2(An, s2));   // B*d1 - A*s2
    bi = ffma2(Bp, s1, fmul2(Ap, d2));   // B*s1 + A*d2
}

template<int CB, int TB>
__device__ __forceinline__ void cu_apply(u64* vr, u64* vi, u64 Ap, u64 An, u64 Bp, u64 Bn, u64 mOne) {
#pragma unroll
    for (int k = 0; k < 16; ++k)
        if ((k & CB) && !(k & TB))
            cu_bfly(vr[k], vi[k], vr[k|TB], vi[k|TB], Ap, An, Bp, Bn, mOne);
}
template<int TB>
__device__ __forceinline__ void rot_apply(u64* vr, u64* vi, const float2* p) {
    M12 m = mkM(p[0], p[1], p[2], p[3]);
#pragma unroll
    for (int k = 0; k < 16; ++k)
        if (!(k & TB))
            bfly(vr[k], vi[k], vr[k|TB], vi[k|TB], m);
}
// lane-mixing scalar butterflies (gate target = amp bit0 = the packed lane)
__device__ __forceinline__ void lane_bfly(u64& r, u64& i,
        float x00, float y00, float x01, float y01,
        float x10, float y10, float x11, float y11) {
    float2 rr = unpk(r), ii = unpk(i);
    float ax = rr.x, bx = rr.y, ay = ii.x, by = ii.y;
    float nax = x00*ax - y00*ay + x01*bx - y01*by;
    float nay = y00*ax + x00*ay + y01*bx + x01*by;
    float nbx = x10*ax - y10*ay + x11*bx - y11*by;
    float nby = y10*ax + x10*ay + y11*bx + x11*by;
    r = pack2(nax, nbx); i = pack2(nay, nby);
}

__device__ __forceinline__ unsigned sw(unsigned i) { return i ^ ((i >> 4) & 15u); }

// pair-index maps for the 3 passes (pair p = amp>>1; pair bit j = amp bit j+1)
__device__ __forceinline__ unsigned idxA(unsigned t, unsigned k) { return (k << 5) | t; }
__device__ __forceinline__ unsigned idxB(unsigned t, unsigned k) { return ((t >> 2) << 6) | (k << 2) | (t & 3); }
__device__ __forceinline__ unsigned idxC(unsigned t, unsigned k) { return (t << 4) | k; }

__global__ void __launch_bounds__(256, 2)
qsim_kernel(const float* __restrict__ x,  const float* __restrict__ W1,
            const float* __restrict__ b1, const float* __restrict__ qw,
            const float* __restrict__ W2)
{
    extern __shared__ u64 smem_u[];
    // layout: re [8][512] u64, im [8][512] u64, rm 200 float2
    const int tid = threadIdx.x;
    const int s   = tid >> 5;      // warp = batch row 0..7
    const int t   = tid & 31;
    const int c   = blockIdx.x;    // circuit

    u64* sre = smem_u + s * 512;
    u64* simm = smem_u + 4096 + s * 512;
    float2* rmp = (float2*)(smem_u + 8192);   // [50][4]

    // rot matrices M = RZ(w2) RY(w1) RZ(w0), shared across the 8 batch-warps
    if (tid < 50) {
        int l = tid / 10, q = tid - l * 10;
        const float* wp = qw + ((c*NLAY + l)*10 + q) * 3;
        float w0 = wp[0], w1v = wp[1], w2 = wp[2];
        float sy, cy; sincosf(0.5f * w1v,       &sy, &cy);
        float sp, cp; sincosf(0.5f * (w0 + w2), &sp, &cp);
        float sm, cm; sincosf(0.5f * (w0 - w2), &sm, &cm);
        rmp[tid*4+0] = make_float2( cy*cp, -cy*sp);
        rmp[tid*4+1] = make_float2(-sy*cm, -sy*sm);
        rmp[tid*4+2] = make_float2( sy*cm, -sy*sm);
        rmp[tid*4+3] = make_float2( cy*cp,  cy*sp);
    }

    float hang = x[s*2+0]*W1[c*2+0] + x[s*2+1]*W1[c*2+1] + b1[c];
    float se, ce;
    sincosf(0.5f * hang, &se, &ce);
    const u64 cep = bc(ce), sep = bc(se), sen = bc(-se);
    const u64 Ap = bc(CU_A), An = bc(-CU_A), Bp = bc(CU_B), Bn = bc(-CU_B);
    const u64 mOne = bc(-1.0f), zero = bc(0.0f);

    __syncthreads();   // rm visible to all warps (only block-wide sync needed)

    u64 vr[16], vi[16];

    for (int l = 0; l < NLAY; ++l) {
        // ===== Pass A: amp bits 9,8,7,6 (k3..k0). qubits 0,1,2 =====
        if (l == 0) {
#pragma unroll
            for (int k = 0; k < 16; ++k) { vr[k] = bc(0.03125f); vi[k] = zero; }
        } else {
#pragma unroll
            for (int k = 0; k < 16; ++k) { unsigned j = sw(idxA(t,k)); vr[k]=sre[j]; vi[k]=simm[j]; }
        }
        // embedding on qubit 0 (k bit3)
        if ((l & 1) == 0) {  // RY
#pragma unroll
            for (int k = 0; k < 8; ++k) {
                u64 ar=vr[k], ai=vi[k], br=vr[k+8], bi=vi[k+8];
                vr[k]   = ffma2(cep, ar, fmul2(sen, br));
                vi[k]   = ffma2(cep, ai, fmul2(sen, bi));
                vr[k+8] = ffma2(sep, ar, fmul2(cep, br));
                vi[k+8] = ffma2(sep, ai, fmul2(cep, bi));
            }
        } else {             // RZ: phase (ce, -se) on bit=0, (ce, se) on bit=1
#pragma unroll
            for (int k = 0; k < 16; ++k) {
                u64 r = vr[k], i = vi[k];
                if (k & 8) { vr[k] = ffma2(cep, r, fmul2(sen, i)); vi[k] = ffma2(cep, i, fmul2(sep, r)); }
                else       { vr[k] = ffma2(cep, r, fmul2(sep, i)); vi[k] = ffma2(cep, i, fmul2(sen, r)); }
            }
        }
        cu_apply<8,4>(vr, vi, Ap, An, Bp, Bn, mOne);   // cu(q0,q1)
        cu_apply<4,2>(vr, vi, Ap, An, Bp, Bn, mOne);   // cu(q1,q2)
        cu_apply<2,1>(vr, vi, Ap, An, Bp, Bn, mOne);   // cu(q2,q3)
        if (l < 4) {
            rot_apply<8>(vr, vi, rmp + (l*10 + 0)*4);
            rot_apply<4>(vr, vi, rmp + (l*10 + 1)*4);
            rot_apply<2>(vr, vi, rmp + (l*10 + 2)*4);
        }
#pragma unroll
        for (int k = 0; k < 16; ++k) { unsigned j = sw(idxA(t,k)); sre[j]=vr[k]; simm[j]=vi[k]; }
        __syncwarp();

        // ===== Pass B: amp bits 6,5,4,3. qubits 3,4,5 =====
#pragma unroll
        for (int k = 0; k < 16; ++k) { unsigned j = sw(idxB(t,k)); vr[k]=sre[j]; vi[k]=simm[j]; }
        cu_apply<8,4>(vr, vi, Ap, An, Bp, Bn, mOne);   // cu(q3,q4)
        cu_apply<4,2>(vr, vi, Ap, An, Bp, Bn, mOne);   // cu(q4,q5)
        cu_apply<2,1>(vr, vi, Ap, An, Bp, Bn, mOne);   // cu(q5,q6)
        if (l < 4) {
            rot_apply<8>(vr, vi, rmp + (l*10 + 3)*4);
            rot_apply<4>(vr, vi, rmp + (l*10 + 4)*4);
            rot_apply<2>(vr, vi, rmp + (l*10 + 5)*4);
        }
#pragma unroll
        for (int k = 0; k < 16; ++k) { unsigned j = sw(idxB(t,k)); sre[j]=vr[k]; simm[j]=vi[k]; }
        __syncwarp();

        // ===== Pass C: amp bits 4,3,2,1 (k3..k0) + lane = amp bit0. qubits 6,7,8,9 =====
#pragma unroll
        for (int k = 0; k < 16; ++k) { unsigned j = sw(idxC(t,k)); vr[k]=sre[j]; vi[k]=simm[j]; }
        cu_apply<4,2>(vr, vi, Ap, An, Bp, Bn, mOne);   // cu(q6,q7)
        cu_apply<2,1>(vr, vi, Ap, An, Bp, Bn, mOne);   // cu(q7,q8)
        // cu(q8,q9): control = k bit0, target = lane
#pragma unroll
        for (int k = 0; k < 16; ++k)
            if (k & 1)
                lane_bfly(vr[k], vi[k], CU_A,CU_A, CU_B,-CU_B, CU_B,CU_B, -CU_A,CU_A);
        if (l < 4) {
            rot_apply<4>(vr, vi, rmp + (l*10 + 6)*4);
            rot_apply<2>(vr, vi, rmp + (l*10 + 7)*4);
            rot_apply<1>(vr, vi, rmp + (l*10 + 8)*4);
            const float2* p = rmp + (l*10 + 9)*4;
            float2 m0=p[0], m1=p[1], m2=p[2], m3=p[3];
#pragma unroll
            for (int k = 0; k < 16; ++k)
                lane_bfly(vr[k], vi[k], m0.x,m0.y, m1.x,m1.y, m2.x,m2.y, m3.x,m3.y);
        }
#pragma unroll
        for (int k = 0; k < 16; ++k) { unsigned j = sw(idxC(t,k)); sre[j]=vr[k]; simm[j]=vi[k]; }
        __syncwarp();
    }

    // ===== Measurement: <Z0> with trailing qubit-0 gate G = H * R * R (R = rm[4][0]) =====
#pragma unroll
    for (int k = 0; k < 16; ++k) { unsigned j = sw(idxA(t,k)); vr[k]=sre[j]; vi[k]=simm[j]; }
    {
        float2 r00 = rmp[160], r01 = rmp[161], r10 = rmp[162], r11 = rmp[163];
        float2 s00 = cadd(cmul(r00,r00), cmul(r01,r10));
        float2 s01 = cadd(cmul(r00,r01), cmul(r01,r11));
        float2 s10 = cadd(cmul(r10,r00), cmul(r11,r10));
        float2 s11 = cadd(cmul(r10,r01), cmul(r11,r11));
        const float is2 = 0.7071067811865476f;
        float2 g00 = make_float2(is2*(s00.x+s10.x), is2*(s00.y+s10.y));
        float2 g01 = make_float2(is2*(s01.x+s11.x), is2*(s01.y+s11.y));
        float2 g10 = make_float2(is2*(s00.x-s10.x), is2*(s00.y-s10.y));
        float2 g11 = make_float2(is2*(s01.x-s11.x), is2*(s01.y-s11.y));
        M12 gm = mkM(g00, g01, g10, g11);
        u64 acc = zero;
#pragma unroll
        for (int k = 0; k < 8; ++k) {
            bfly(vr[k], vi[k], vr[k|8], vi[k|8], gm);
            acc = ffma2(vr[k],   vr[k],   acc);
            acc = ffma2(vi[k],   vi[k],   acc);
            acc = ffma2(neg2(vr[k|8]), vr[k|8], acc);
            acc = ffma2(neg2(vi[k|8]), vi[k|8], acc);
        }
        float2 av = unpk(acc);
        float z = av.x + av.y;
#pragma unroll
        for (int off = 16; off > 0; off >>= 1) z += __shfl_down_sync(0xffffffffu, z, off);
        if (t == 0) {
            atomicAdd(&g_acc[s*2 + 0], z * W2[c]);
            atomicAdd(&g_acc[s*2 + 1], z * W2[NC + c]);
        }
    }
}

__global__ void finalize_kernel(const float* __restrict__ b2, float* __restrict__ out) {
    int b = threadIdx.x;
    if (b < 8) {
        float l0 = g_acc[2*b]   + b2[0];
        float l1 = g_acc[2*b+1] + b2[1];
        float m  = fmaxf(l0, l1);
        float e0 = expf(l0 - m), e1 = expf(l1 - m);
        float inv = 1.0f / (e0 + e1);
        out[2*b + 0] = e0 * inv;
        out[2*b + 1] = e1 * inv;
        g_acc[2*b]   = 0.0f;   // self-reset for next graph replay
        g_acc[2*b+1] = 0.0f;
    }
}

extern "C" void kernel_launch(void* const* d_in, const int* in_sizes, int n_in,
                              void* d_out, int out_size) {
    const float* x  = (const float*)d_in[0];   // (8,2)
    const float* W1 = (const float*)d_in[1];   // (320,2)
    const float* b1 = (const float*)d_in[2];   // (320,)
    const float* qw = (const float*)d_in[3];   // (320,5,10,3)
    const float* W2 = (const float*)d_in[4];   // (2,320)
    const float* b2 = (const float*)d_in[5];   // (2,)
    float* out = (float*)d_out;                // (8,2)

    const int smem = 8 * 512 * 2 * sizeof(unsigned long long) + 200 * sizeof(float2);
    cudaFuncSetAttribute(qsim_kernel, cudaFuncAttributeMaxDynamicSharedMemorySize, smem);
    qsim_kernel<<<320, 256, smem>>>(x, W1, b1, qw, W2);
    finalize_kernel<<<1, 32>>>(b2, out);
}

// round 4
// speedup vs baseline: 1.6706x; 1.3686x over previous
#include <cuda_runtime.h>

// Hybrid quantum model, v3: packed f32x2, warp-private states, cross-layer
// gate merging (rot folded into next layer's controlled gates), single launch.

#define NC   320
#define NLAY 5

typedef unsigned long long u64;

__device__ float g_acc[16];          // partial logits [batch][2]
__device__ unsigned int g_done;      // CTA completion counter

// ---------------- packed f32x2 helpers ----------------
__device__ __forceinline__ u64 pack2(float x, float y) {
    u64 u; asm("mov.b64 %0,{%1,%2};" : "=l"(u) : "f"(x), "f"(y)); return u;
}
__device__ __forceinline__ float2 unpk(u64 u) {
    float2 v; asm("mov.b64 {%0,%1},%2;" : "=f"(v.x), "=f"(v.y) : "l"(u)); return v;
}
__device__ __forceinline__ u64 bc(float x) { return pack2(x, x); }
__device__ __forceinline__ u64 ffma2(u64 a, u64 b, u64 c) {
    u64 d; asm("fma.rn.f32x2 %0,%1,%2,%3;" : "=l"(d) : "l"(a), "l"(b), "l"(c)); return d;
}
__device__ __forceinline__ u64 fmul2(u64 a, u64 b) {
    u64 d; asm("mul.rn.f32x2 %0,%1,%2;" : "=l"(d) : "l"(a), "l"(b)); return d;
}
__device__ __forceinline__ u64 fadd2(u64 a, u64 b) {
    u64 d; asm("add.rn.f32x2 %0,%1,%2;" : "=l"(d) : "l"(a), "l"(b)); return d;
}
__device__ __forceinline__ u64 neg2(u64 a) { return a ^ 0x8000000080000000ull; }

__device__ __forceinline__ float2 cmul(float2 a, float2 b) {
    return make_float2(a.x*b.x - a.y*b.y, a.x*b.y + a.y*b.x);
}
__device__ __forceinline__ float2 cadd(float2 a, float2 b) {
    return make_float2(a.x + b.x, a.y + b.y);
}

// general complex 2x2 butterfly on packed pairs
struct M12 { u64 x00,y00,yn00,x01,y01,yn01,x10,y10,yn10,x11,y11,yn11; };

__device__ __forceinline__ M12 mkM(float2 m00, float2 m01, float2 m10, float2 m11) {
    M12 m;
    m.x00=bc(m00.x); m.y00=bc(m00.y); m.yn00=bc(-m00.y);
    m.x01=bc(m01.x); m.y01=bc(m01.y); m.yn01=bc(-m01.y);
    m.x10=bc(m10.x); m.y10=bc(m10.y); m.yn10=bc(-m10.y);
    m.x11=bc(m11.x); m.y11=bc(m11.y); m.yn11=bc(-m11.y);
    return m;
}
__device__ __forceinline__ void bfly(u64& ar, u64& ai, u64& br, u64& bi, const M12& m) {
    u64 nar = ffma2(m.x00,ar, ffma2(m.yn00,ai, ffma2(m.x01,br, fmul2(m.yn01,bi))));
    u64 nai = ffma2(m.y00,ar, ffma2(m.x00, ai, ffma2(m.y01,br, fmul2(m.x01, bi))));
    u64 nbr = ffma2(m.x10,ar, ffma2(m.yn10,ai, ffma2(m.x11,br, fmul2(m.yn11,bi))));
    u64 nbi = ffma2(m.y10,ar, ffma2(m.x10, ai, ffma2(m.y11,br, fmul2(m.x11, bi))));
    ar=nar; ai=nai; br=nbr; bi=nbi;
}

// CU gate = RY(pi/4)RZ(pi/2)X: u00=(A,A) u01=(B,-B) u10=(B,B) u11=(-A,A)
#define CU_A (-0.2705980500730985f)
#define CU_B ( 0.6532814824381883f)
__device__ __forceinline__ void cu_bfly(u64& ar, u64& ai, u64& br, u64& bi,
                                        u64 Ap, u64 An, u64 Bp, u64 Bn, u64 mOne) {
    u64 d1 = ffma2(mOne, ai, ar);
    u64 s1 = fadd2(ar, ai);
    u64 s2 = fadd2(br, bi);
    u64 d2 = ffma2(mOne, bi, br);
    ar = ffma2(Ap, d1, fmul2(Bp, s2));
    ai = ffma2(Ap, s1, fmul2(Bn, d2));
    br = ffma2(Bp, d1, fmul2(An, s2));
    bi = ffma2(Bp, s1, fmul2(Ap, d2));
}
template<int CB, int TB>
__device__ __forceinline__ void cu_apply(u64* vr, u64* vi, u64 Ap, u64 An, u64 Bp, u64 Bn, u64 mOne) {
#pragma unroll
    for (int k = 0; k < 16; ++k)
        if ((k & CB) && !(k & TB))
            cu_bfly(vr[k], vi[k], vr[k|TB], vi[k|TB], Ap, An, Bp, Bn, mOne);
}

// merged gate CU(c,t) * (I ⊗ R(t)): control=1 pairs get U·R, control=0 pairs get R
template<int CB, int TB>
__device__ __forceinline__ void merged_cu(u64* vr, u64* vi, const float2* pR, const float2* pUR) {
    {
        M12 m = mkM(pUR[0], pUR[1], pUR[2], pUR[3]);
#pragma unroll
        for (int k = 0; k < 16; ++k)
            if (!(k & TB) && (k & CB))
                bfly(vr[k], vi[k], vr[k|TB], vi[k|TB], m);
    }
    {
        M12 m = mkM(pR[0], pR[1], pR[2], pR[3]);
#pragma unroll
        for (int k = 0; k < 16; ++k)
            if (!(k & TB) && !(k & CB))
                bfly(vr[k], vi[k], vr[k|TB], vi[k|TB], m);
    }
}

// lane-mixing scalar butterfly (target = packed lane = amp bit0)
__device__ __forceinline__ void lane_bfly(u64& r, u64& i,
        float x00, float y00, float x01, float y01,
        float x10, float y10, float x11, float y11) {
    float2 rr = unpk(r), ii = unpk(i);
    float ax = rr.x, bx = rr.y, ay = ii.x, by = ii.y;
    float nax = x00*ax - y00*ay + x01*bx - y01*by;
    float nay = y00*ax + x00*ay + y01*bx + x01*by;
    float nbx = x10*ax - y10*ay + x11*bx - y11*by;
    float nby = y10*ax + x10*ay + y11*bx + x11*by;
    r = pack2(nax, nbx); i = pack2(nay, nby);
}
__device__ __forceinline__ void lane_bfly_m(u64& r, u64& i, const float2* p) {
    lane_bfly(r, i, p[0].x,p[0].y, p[1].x,p[1].y, p[2].x,p[2].y, p[3].x,p[3].y);
}

__device__ __forceinline__ unsigned sw(unsigned i) { return i ^ ((i >> 4) & 15u); }
__device__ __forceinline__ unsigned idxA(unsigned t, unsigned k) { return (k << 5) | t; }
__device__ __forceinline__ unsigned idxB(unsigned t, unsigned k) { return ((t >> 2) << 6) | (k << 2) | (t & 3); }
__device__ __forceinline__ unsigned idxC(unsigned t, unsigned k) { return (t << 4) | k; }

__global__ void __launch_bounds__(128, 4)
qsim_kernel(const float* __restrict__ x,  const float* __restrict__ W1,
            const float* __restrict__ b1, const float* __restrict__ qw,
            const float* __restrict__ W2, const float* __restrict__ b2,
            float* __restrict__ out)
{
    extern __shared__ u64 smem_u[];
    const int tid = threadIdx.x;
    const int s   = tid >> 5;           // warp 0..3
    const int t   = tid & 31;
    const int c   = blockIdx.x >> 1;    // circuit
    const int b   = (blockIdx.x & 1) * 4 + s;  // batch row 0..7

    u64* sre  = smem_u + s * 512;
    u64* simm = smem_u + 2048 + s * 512;
    float2* Rm  = (float2*)(smem_u + 4096);  // [50][4]
    float2* URm = Rm + 200;                  // [40][4]  (l=0..3, q=0..9; q0 unused)

    // R_{l,q} = RZ(w2) RY(w1) RZ(w0)
    if (tid < 50) {
        int l = tid / 10, q = tid - l * 10;
        const float* wp = qw + ((c*NLAY + l)*10 + q) * 3;
        float w0 = wp[0], w1v = wp[1], w2v = wp[2];
        float sy, cy; sincosf(0.5f * w1v,        &sy, &cy);
        float sp, cp; sincosf(0.5f * (w0 + w2v), &sp, &cp);
        float sm, cm; sincosf(0.5f * (w0 - w2v), &sm, &cm);
        Rm[tid*4+0] = make_float2( cy*cp, -cy*sp);
        Rm[tid*4+1] = make_float2(-sy*cm, -sy*sm);
        Rm[tid*4+2] = make_float2( sy*cm, -sy*sm);
        Rm[tid*4+3] = make_float2( cy*cp,  cy*sp);
    }
    __syncthreads();
    // UR_{l,q} = U * R_{l,q}
    if (tid < 40 && (tid % 10) != 0) {
        const float2 u00 = make_float2(CU_A,  CU_A);
        const float2 u01 = make_float2(CU_B, -CU_B);
        const float2 u10 = make_float2(CU_B,  CU_B);
        const float2 u11 = make_float2(-CU_A, CU_A);
        float2 r00 = Rm[tid*4+0], r01 = Rm[tid*4+1], r10 = Rm[tid*4+2], r11 = Rm[tid*4+3];
        URm[tid*4+0] = cadd(cmul(u00, r00), cmul(u01, r10));
        URm[tid*4+1] = cadd(cmul(u00, r01), cmul(u01, r11));
        URm[tid*4+2] = cadd(cmul(u10, r00), cmul(u11, r10));
        URm[tid*4+3] = cadd(cmul(u10, r01), cmul(u11, r11));
    }

    float hang = x[b*2+0]*W1[c*2+0] + x[b*2+1]*W1[c*2+1] + b1[c];
    float se, ce;
    sincosf(0.5f * hang, &se, &ce);
    const u64 cep = bc(ce), sep = bc(se), sen = bc(-se);
    const u64 Ap = bc(CU_A), An = bc(-CU_A), Bp = bc(CU_B), Bn = bc(-CU_B);
    const u64 mOne = bc(-1.0f), zero = bc(0.0f);

    __syncthreads();

    u64 vr[16], vi[16];

    for (int l = 0; l < NLAY; ++l) {
        const float2* Rp  = Rm  + (l-1)*40;   // R_{l-1,q}*4 base (valid l>=1)
        const float2* URp = URm + (l-1)*40;

        // ===== Pass A: qubits 0-3 =====
        if (l == 0) {
#pragma unroll
            for (int k = 0; k < 16; ++k) { vr[k] = bc(0.03125f); vi[k] = zero; }
            // bare RY embedding on qubit 0 (mask 8)
#pragma unroll
            for (int k = 0; k < 8; ++k) {
                u64 ar=vr[k], ai=vi[k], br=vr[k+8], bi=vi[k+8];
                vr[k]   = ffma2(cep, ar, fmul2(sen, br));
                vi[k]   = ffma2(cep, ai, fmul2(sen, bi));
                vr[k+8] = ffma2(sep, ar, fmul2(cep, br));
                vi[k+8] = ffma2(sep, ai, fmul2(cep, bi));
            }
            cu_apply<8,4>(vr, vi, Ap, An, Bp, Bn, mOne);
            cu_apply<4,2>(vr, vi, Ap, An, Bp, Bn, mOne);
            cu_apply<2,1>(vr, vi, Ap, An, Bp, Bn, mOne);
        } else {
#pragma unroll
            for (int k = 0; k < 16; ++k) { unsigned j = sw(idxA(t,k)); vr[k]=sre[j]; vi[k]=simm[j]; }
            // merged embedding: E = emb_l * R_{l-1,0}
            float2 r00 = Rp[0], r01 = Rp[1], r10 = Rp[2], r11 = Rp[3];
            float2 e00, e01, e10, e11;
            if ((l & 1) == 0) {  // RY (real)
                e00 = make_float2(ce*r00.x - se*r10.x, ce*r00.y - se*r10.y);
                e01 = make_float2(ce*r01.x - se*r11.x, ce*r01.y - se*r11.y);
                e10 = make_float2(se*r00.x + ce*r10.x, se*r00.y + ce*r10.y);
                e11 = make_float2(se*r01.x + ce*r11.x, se*r01.y + ce*r11.y);
            } else {             // RZ diag((ce,-se),(ce,se))
                float2 f0 = make_float2(ce, -se), f1 = make_float2(ce, se);
                e00 = cmul(f0, r00); e01 = cmul(f0, r01);
                e10 = cmul(f1, r10); e11 = cmul(f1, r11);
            }
            M12 me = mkM(e00, e01, e10, e11);
#pragma unroll
            for (int k = 0; k < 8; ++k)
                bfly(vr[k], vi[k], vr[k+8], vi[k+8], me);
            merged_cu<8,4>(vr, vi, Rp + 1*4, URp + 1*4);
            merged_cu<4,2>(vr, vi, Rp + 2*4, URp + 2*4);
            merged_cu<2,1>(vr, vi, Rp + 3*4, URp + 3*4);
        }
#pragma unroll
        for (int k = 0; k < 16; ++k) { unsigned j = sw(idxA(t,k)); sre[j]=vr[k]; simm[j]=vi[k]; }
        __syncwarp();

        // ===== Pass B: qubits 3-6 =====
#pragma unroll
        for (int k = 0; k < 16; ++k) { unsigned j = sw(idxB(t,k)); vr[k]=sre[j]; vi[k]=simm[j]; }
        if (l == 0) {
            cu_apply<8,4>(vr, vi, Ap, An, Bp, Bn, mOne);
            cu_apply<4,2>(vr, vi, Ap, An, Bp, Bn, mOne);
            cu_apply<2,1>(vr, vi, Ap, An, Bp, Bn, mOne);
        } else {
            merged_cu<8,4>(vr, vi, Rp + 4*4, URp + 4*4);
            merged_cu<4,2>(vr, vi, Rp + 5*4, URp + 5*4);
            merged_cu<2,1>(vr, vi, Rp + 6*4, URp + 6*4);
        }
#pragma unroll
        for (int k = 0; k < 16; ++k) { unsigned j = sw(idxB(t,k)); sre[j]=vr[k]; simm[j]=vi[k]; }
        __syncwarp();

        // ===== Pass C: qubits 6-9 (lane = qubit 9) =====
#pragma unroll
        for (int k = 0; k < 16; ++k) { unsigned j = sw(idxC(t,k)); vr[k]=sre[j]; vi[k]=simm[j]; }
        if (l == 0) {
            cu_apply<4,2>(vr, vi, Ap, An, Bp, Bn, mOne);
            cu_apply<2,1>(vr, vi, Ap, An, Bp, Bn, mOne);
#pragma unroll
            for (int k = 0; k < 16; ++k)
                if (k & 1)
                    lane_bfly(vr[k], vi[k], CU_A,CU_A, CU_B,-CU_B, CU_B,CU_B, -CU_A,CU_A);
        } else {
            merged_cu<4,2>(vr, vi, Rp + 7*4, URp + 7*4);
            merged_cu<2,1>(vr, vi, Rp + 8*4, URp + 8*4);
            // merged cu(8,9): control = k bit0, target = lane
#pragma unroll
            for (int k = 0; k < 16; ++k) {
                if (k & 1) lane_bfly_m(vr[k], vi[k], URp + 9*4);
                else       lane_bfly_m(vr[k], vi[k], Rp  + 9*4);
            }
        }
#pragma unroll
        for (int k = 0; k < 16; ++k) { unsigned j = sw(idxC(t,k)); sre[j]=vr[k]; simm[j]=vi[k]; }
        __syncwarp();
    }

    // ===== Measurement: <Z0> with trailing qubit-0 gate G = H * R * R, R = R_{4,0} =====
#pragma unroll
    for (int k = 0; k < 16; ++k) { unsigned j = sw(idxA(t,k)); vr[k]=sre[j]; vi[k]=simm[j]; }
    float z;
    {
        float2 r00 = Rm[160], r01 = Rm[161], r10 = Rm[162], r11 = Rm[163];
        float2 s00 = cadd(cmul(r00,r00), cmul(r01,r10));
        float2 s01 = cadd(cmul(r00,r01), cmul(r01,r11));
        float2 s10 = cadd(cmul(r10,r00), cmul(r11,r10));
        float2 s11 = cadd(cmul(r10,r01), cmul(r11,r11));
        const float is2 = 0.7071067811865476f;
        float2 g00 = make_float2(is2*(s00.x+s10.x), is2*(s00.y+s10.y));
        float2 g01 = make_float2(is2*(s01.x+s11.x), is2*(s01.y+s11.y));
        float2 g10 = make_float2(is2*(s00.x-s10.x), is2*(s00.y-s10.y));
        float2 g11 = make_float2(is2*(s01.x-s11.x), is2*(s01.y-s11.y));
        M12 gm = mkM(g00, g01, g10, g11);
        u64 acc = zero;
#pragma unroll
        for (int k = 0; k < 8; ++k) {
            bfly(vr[k], vi[k], vr[k|8], vi[k|8], gm);
            acc = ffma2(vr[k],   vr[k],   acc);
            acc = ffma2(vi[k],   vi[k],   acc);
            acc = ffma2(neg2(vr[k|8]), vr[k|8], acc);
            acc = ffma2(neg2(vi[k|8]), vi[k|8], acc);
        }
        float2 av = unpk(acc);
        z = av.x + av.y;
#pragma unroll
        for (int off = 16; off > 0; off >>= 1) z += __shfl_down_sync(0xffffffffu, z, off);
    }
    if (t == 0) {
        atomicAdd(&g_acc[b*2 + 0], z * W2[c]);
        atomicAdd(&g_acc[b*2 + 1], z * W2[NC + c]);
    }
    __syncthreads();

    // last CTA finalizes: softmax + output + reset
    if (tid == 0) {
        __threadfence();
        unsigned int done = atomicAdd(&g_done, 1u);
        if (done == gridDim.x - 1) {
            __threadfence();
#pragma unroll
            for (int bb = 0; bb < 8; ++bb) {
                float l0 = g_acc[2*bb]   + b2[0];
                float l1 = g_acc[2*bb+1] + b2[1];
                float m  = fmaxf(l0, l1);
                float e0 = expf(l0 - m), e1 = expf(l1 - m);
                float inv = 1.0f / (e0 + e1);
                out[2*bb + 0] = e0 * inv;
                out[2*bb + 1] = e1 * inv;
                g_acc[2*bb]   = 0.0f;
                g_acc[2*bb+1] = 0.0f;
            }
            g_done = 0u;
            __threadfence();
        }
    }
}

extern "C" void kernel_launch(void* const* d_in, const int* in_sizes, int n_in,
                              void* d_out, int out_size) {
    const float* x  = (const float*)d_in[0];   // (8,2)
    const float* W1 = (const float*)d_in[1];   // (320,2)
    const float* b1 = (const float*)d_in[2];   // (320,)
    const float* qw = (const float*)d_in[3];   // (320,5,10,3)
    const float* W2 = (const float*)d_in[4];   // (2,320)
    const float* b2 = (const float*)d_in[5];   // (2,)
    float* out = (float*)d_out;                // (8,2)

    const int smem = 4096 * sizeof(unsigned long long) + 360 * sizeof(float2);
    cudaFuncSetAttribute(qsim_kernel, cudaFuncAttributeMaxDynamicSharedMemorySize, smem);
    qsim_kernel<<<640, 128, smem>>>(x, W1, b1, qw, W2, b2, out);
}